// round 4
// baseline (speedup 1.0000x reference)
#include <cuda_runtime.h>
#include <math.h>
#include <stdint.h>

#define NSNR 2048
#define NT   4096
#define NP   100
#define NI   99
#define TPB  256
#define VPT  (NT / TPB)   // 16
#define NWARP (TPB / 32)
#define NACC 32

__device__ double       g_acc[NACC];   // zero-init; reset by last block each run
__device__ unsigned int g_ticket;      // self-resetting via atomicInc wrap

// Precomputed Thomas forward-elimination multipliers for tri(1,4,1), n=98.
struct CpTab { float v[98]; };
static constexpr CpTab make_cp() {
    CpTab t{};
    double c = 0.25;
    t.v[0] = (float)c;
    for (int i = 1; i < 98; i++) { c = 1.0 / (4.0 - c); t.v[i] = (float)c; }
    return t;
}
__constant__ CpTab d_cp = make_cp();

// ---------------------------------------------------------------------------
__device__ __forceinline__ uint32_t smem_u32(const void* p) {
    return (uint32_t)__cvta_generic_to_shared(p);
}
__device__ __forceinline__ void cp_async16(uint32_t saddr, const void* gptr) {
    asm volatile("cp.async.cg.shared.global [%0], [%1], 16;" :: "r"(saddr), "l"(gptr));
}
__device__ __forceinline__ void cp_commit() {
    asm volatile("cp.async.commit_group;");
}
template <int N> __device__ __forceinline__ void cp_wait() {
    asm volatile("cp.async.wait_group %0;" :: "n"(N));
}

// Chunk-level (16B) XOR swizzle: conflict-free for striped float4 writes AND
// blocked float4 reads (verified per 8-thread LDS.128 phase).
__device__ __forceinline__ int swzc(int c) { return c ^ ((c >> 3) & 3); }
__device__ __forceinline__ float ld_elem(const float4* sv, int e) {
    return reinterpret_cast<const float*>(sv)[4 * swzc(e >> 2) + (e & 3)];
}

// Block-wide exclusive scan of one float per thread. Contains __syncthreads.
__device__ __forceinline__ float block_scan_excl(float v, float* warp_sums, float* total) {
    int lane = threadIdx.x & 31, wid = threadIdx.x >> 5;
    float x = v;
#pragma unroll
    for (int o = 1; o < 32; o <<= 1) {
        float y = __shfl_up_sync(0xffffffffu, x, o);
        if (lane >= o) x += y;
    }
    if (lane == 31) warp_sums[wid] = x;
    __syncthreads();
    if (wid == 0) {
        float w = (lane < NWARP) ? warp_sums[lane] : 0.0f;
#pragma unroll
        for (int o = 1; o < NWARP; o <<= 1) {
            float y = __shfl_up_sync(0xffffffffu, w, o);
            if (lane >= o) w += y;
        }
        if (lane < NWARP) warp_sums[lane] = w;
    }
    __syncthreads();
    float excl = (x - v) + (wid ? warp_sums[wid - 1] : 0.0f);
    *total = warp_sums[NWARP - 1];
    return excl;
}

// Emit all quantiles k whose target p_k*T lies in [Sj, Sj1) for interval j.
__device__ __forceinline__ void emit_quantiles(
    float Sj, float Sj1, int j, float total, float sc99, float dt, float* sQ)
{
    float qlo = Sj * sc99;
    float qhi = Sj1 * sc99;
    int kst = (int)ceilf(qlo);
    int ken = (j == NT - 2) ? 99 : ((int)ceilf(qhi) - 1);
    kst = max(kst, 0);
    ken = min(ken, 99);
    if (kst <= ken) {
        float den = Sj1 - Sj;
        float rden = (den > 0.0f) ? (dt / den) : 0.0f;
        float jdt = (float)j * dt;
        for (int k = kst; k <= ken; k++) {
            float target = ((float)k / 99.0f) * total;
            sQ[k] = fmaf(target - Sj, rden, jdt);
        }
    }
}

// ---------------------------------------------------------------------------
// Fully fused: obs -> spline; f -> loss; global reduction via atomics.
// ---------------------------------------------------------------------------
__global__ void __launch_bounds__(TPB, 6) wasserstein_kernel(
    const float* __restrict__ f, const float* __restrict__ obs,
    const float* __restrict__ t, float* __restrict__ out)
{
    __shared__ float4 svA4[NT / 4];      // raw obs (swizzled chunks)
    __shared__ float4 svF4[NT / 4];      // raw f   (swizzled chunks)
    __shared__ float4 scf4[NP];          // spline coeffs (a,b,c,d)
    __shared__ float  sQ[NP];
    __shared__ float  sM[NP];
    __shared__ float  sdp[98];
    __shared__ float  firstS[TPB];       // S at each thread's first element
    __shared__ float  warp_sums[NWARP];
    __shared__ float  red[NWARP];

    const int   row  = blockIdx.x;
    const float dt   = t[1] - t[0];
    const int   base = threadIdx.x * VPT;

    // ---- issue ALL DRAM traffic for this block up front (cp.async) ----
    {
        const float4* go = reinterpret_cast<const float4*>(obs + (size_t)row * NT);
        const float4* gf = reinterpret_cast<const float4*>(f   + (size_t)row * NT);
        uint32_t sa = smem_u32(svA4);
        uint32_t sf = smem_u32(svF4);
#pragma unroll
        for (int i = 0; i < 4; i++) {
            int j = threadIdx.x + TPB * i;
            cp_async16(sa + 16u * swzc(j), go + j);
        }
        cp_commit();
#pragma unroll
        for (int i = 0; i < 4; i++) {
            int j = threadIdx.x + TPB * i;
            cp_async16(sf + 16u * swzc(j), gf + j);
        }
        cp_commit();
    }

    // ================= Phase A: obs -> spline coefficients =================
    cp_wait<1>();
    __syncthreads();

    float absv[VPT];
#pragma unroll
    for (int q = 0; q < VPT / 4; q++) {
        float4 v = svA4[swzc((base >> 2) + q)];
        absv[4 * q + 0] = fabsf(v.x);
        absv[4 * q + 1] = fabsf(v.y);
        absv[4 * q + 2] = fabsf(v.z);
        absv[4 * q + 3] = fabsf(v.w);
    }
    float prevAbs = (base == 0) ? 0.0f : fabsf(ld_elem(svA4, base - 1));

    float run = 0.0f;
    {
        float p = prevAbs;
#pragma unroll
        for (int k = 0; k < VPT; k++) {
            float cur = absv[k];
            float e = (base + k == 0) ? 0.0f : 0.5f * dt * (cur + p);
            run += e;
            p = cur;
        }
    }
    float total;
    float excl = block_scan_excl(run, warp_sums, &total);

    // publish S at first element for boundary consistency
    float inc0 = (base == 0) ? 0.0f : 0.5f * dt * (absv[0] + prevAbs);
    float s0 = excl + inc0;
    firstS[threadIdx.x] = s0;
    __syncthreads();
    float nextS = (threadIdx.x < TPB - 1) ? firstS[threadIdx.x + 1] : total;

    // direct quantile emission (replaces CDF store + binary search)
    {
        float sc99 = 99.0f / total;
        float Scur = s0;
        float p = absv[0];
#pragma unroll
        for (int k = 1; k < VPT; k++) {
            float cur = absv[k];
            float Snext = Scur + 0.5f * dt * (cur + p);
            emit_quantiles(Scur, Snext, base + k - 1, total, sc99, dt, sQ);
            Scur = Snext;
            p = cur;
        }
        if (threadIdx.x < TPB - 1)
            emit_quantiles(Scur, nextS, base + VPT - 1, total, sc99, dt, sQ);
    }
    __syncthreads();

    // u_i = rhs_i * cp_i in parallel (98 threads)
    if (threadIdx.x < 98) {
        int i = threadIdx.x;
        const float S = 6.0f * 9801.0f;   // 6 / h^2
        float rhs = S * (sQ[i + 2] - 2.0f * sQ[i + 1] + sQ[i]);
        sdp[i] = rhs * d_cp.v[i];
    }
    __syncthreads();

    // serial Thomas recurrences (single FFMA chains)
    if (threadIdx.x == 0) {
        float dp = sdp[0];
        for (int i = 1; i < 98; i++) {
            dp = fmaf(-d_cp.v[i], dp, sdp[i]);
            sdp[i] = dp;
        }
        sM[0] = 0.0f;
        sM[NP - 1] = 0.0f;
        float mnext = sdp[97];
        sM[98] = mnext;
        for (int i = 96; i >= 0; i--) {
            mnext = fmaf(-d_cp.v[i], mnext, sdp[i]);
            sM[i + 1] = mnext;
        }
    }
    __syncthreads();

    if (threadIdx.x < NI) {
        int i = threadIdx.x;
        const float H    = (float)(1.0 / 99.0);
        const float invH = 99.0f;
        float Mi = sM[i], Mi1 = sM[i + 1];
        float4 c;
        c.x = sQ[i];
        c.y = (sQ[i + 1] - sQ[i]) * invH - H * (2.0f * Mi + Mi1) * (1.0f / 6.0f);
        c.z = Mi * 0.5f;
        c.w = (Mi1 - Mi) * (invH / 6.0f);
        scf4[i] = c;
    }
    __syncthreads();

    // ================= Phase B: f -> loss contribution =================
    cp_wait<0>();
    __syncthreads();

#pragma unroll
    for (int q = 0; q < VPT / 4; q++) {
        float4 v = svF4[swzc((base >> 2) + q)];
        absv[4 * q + 0] = fabsf(v.x);
        absv[4 * q + 1] = fabsf(v.y);
        absv[4 * q + 2] = fabsf(v.z);
        absv[4 * q + 3] = fabsf(v.w);
    }
    prevAbs = (base == 0) ? 0.0f : fabsf(ld_elem(svF4, base - 1));

    run = 0.0f;
    {
        float p = prevAbs;
#pragma unroll
        for (int k = 0; k < VPT; k++) {
            float cur = absv[k];
            float e = (base + k == 0) ? 0.0f : 0.5f * dt * (cur + p);
            run += e;
            p = cur;
        }
    }
    excl = block_scan_excl(run, warp_sums, &total);

    const float invT = 1.0f / total;
    float gsum = 0.0f;
    {
        float p = prevAbs, r2 = 0.0f;
#pragma unroll
        for (int k = 0; k < VPT; k++) {
            int j = base + k;
            float cur = absv[k];
            float e = (j == 0) ? 0.0f : 0.5f * dt * (cur + p);
            r2 += e;
            p = cur;

            float F  = (r2 + excl) * invT;
            float xi = fminf(fmaxf(F, 0.0f), 1.0f);
            int idx  = min((int)(xi * 99.0f), NI - 1);
            float dx = xi - (float)idx * (float)(1.0 / 99.0);
            float4 cf = scf4[idx];
            float val = cf.x + dx * (cf.y + dx * (cf.z + dx * cf.w));
            float tj  = (float)j * dt;
            float diff = tj - val;
            float g = diff * diff * (cur * invT);
            gsum += g;
            if (j == 0 || j == NT - 1) gsum -= 0.5f * g;   // trapezoid edges
        }
    }

#pragma unroll
    for (int o = 16; o; o >>= 1) gsum += __shfl_down_sync(0xffffffffu, gsum, o);
    if ((threadIdx.x & 31) == 0) red[threadIdx.x >> 5] = gsum;
    __syncthreads();

    if (threadIdx.x == 0) {
        float s = 0.0f;
#pragma unroll
        for (int w = 0; w < NWARP; w++) s += red[w];
        double my = (double)(dt * s);
        atomicAdd(&g_acc[row & (NACC - 1)], my);
        __threadfence();
        unsigned tk = atomicInc(&g_ticket, NSNR - 1);   // wraps to 0 automatically
        if (tk == NSNR - 1) {
            double tot = 0.0;
#pragma unroll
            for (int w = 0; w < NACC; w++) { tot += g_acc[w]; g_acc[w] = 0.0; }
            out[0] = (float)tot;
        }
    }
}

// ---------------------------------------------------------------------------
extern "C" void kernel_launch(void* const* d_in, const int* in_sizes, int n_in,
                              void* d_out, int out_size)
{
    const float* f   = (const float*)d_in[0];
    const float* obs = (const float*)d_in[1];
    const float* t   = (const float*)d_in[2];

    wasserstein_kernel<<<NSNR, TPB>>>(f, obs, t, (float*)d_out);
}

// round 5
// speedup vs baseline: 1.3125x; 1.3125x over previous
#include <cuda_runtime.h>
#include <math.h>
#include <stdint.h>

#define NSNR 2048
#define NT   4096
#define NP   100
#define NI   99
#define TPB  256
#define NC   (NT / 4)      // 1024 chunks of 4 elements
#define CPT  (NC / TPB)    // 4 chunks per thread
#define NWARP (TPB / 32)
#define NACC 32

__device__ double       g_acc[NACC];   // zero-init; reset by last block each run
__device__ unsigned int g_ticket;      // self-resetting via atomicInc wrap

// Precomputed Thomas forward-elimination multipliers for tri(1,4,1), n=98.
struct CpTab { float v[98]; };
static constexpr CpTab make_cp() {
    CpTab t{};
    double c = 0.25;
    t.v[0] = (float)c;
    for (int i = 1; i < 98; i++) { c = 1.0 / (4.0 - c); t.v[i] = (float)c; }
    return t;
}
__constant__ CpTab d_cp = make_cp();

// Block-wide exclusive scan of one float per thread. Contains __syncthreads.
__device__ __forceinline__ float block_scan_excl(float v, float* warp_sums, float* total) {
    int lane = threadIdx.x & 31, wid = threadIdx.x >> 5;
    float x = v;
#pragma unroll
    for (int o = 1; o < 32; o <<= 1) {
        float y = __shfl_up_sync(0xffffffffu, x, o);
        if (lane >= o) x += y;
    }
    if (lane == 31) warp_sums[wid] = x;
    __syncthreads();
    if (wid == 0) {
        float w = (lane < NWARP) ? warp_sums[lane] : 0.0f;
#pragma unroll
        for (int o = 1; o < NWARP; o <<= 1) {
            float y = __shfl_up_sync(0xffffffffu, w, o);
            if (lane >= o) w += y;
        }
        if (lane < NWARP) warp_sums[lane] = w;
    }
    __syncthreads();
    float excl = (x - v) + (wid ? warp_sums[wid - 1] : 0.0f);
    *total = warp_sums[NWARP - 1];
    return excl;
}

// ---------------------------------------------------------------------------
// Striped load of |src| into fa[CPT][4] registers + two-level chunk scan.
// On exit: pfx[i] = exclusive prefix of increments at the start of chunk
// (tid + TPB*i); sLa[c] = last |x| of chunk c; *totalp = row total.
// Contains multiple __syncthreads.
// ---------------------------------------------------------------------------
__device__ __forceinline__ void chunk_scan(
    const float4* __restrict__ src4, float dt,
    float fa[CPT][4], float pfx[CPT],
    float* sCh, float* sLa, float* warp_sums, float* totalp)
{
    const int tid = threadIdx.x;
#pragma unroll
    for (int i = 0; i < CPT; i++) {
        float4 v = src4[tid + TPB * i];
        fa[i][0] = fabsf(v.x);
        fa[i][1] = fabsf(v.y);
        fa[i][2] = fabsf(v.z);
        fa[i][3] = fabsf(v.w);
        sLa[tid + TPB * i] = fa[i][3];
    }
    __syncthreads();

#pragma unroll
    for (int i = 0; i < CPT; i++) {
        int c = tid + TPB * i;
        float prev = (c == 0) ? 0.0f : sLa[c - 1];
        float e0 = (c == 0) ? 0.0f : 0.5f * dt * (fa[i][0] + prev);
        float e1 = 0.5f * dt * (fa[i][1] + fa[i][0]);
        float e2 = 0.5f * dt * (fa[i][2] + fa[i][1]);
        float e3 = 0.5f * dt * (fa[i][3] + fa[i][2]);
        sCh[c] = ((e0 + e1) + e2) + e3;
    }
    __syncthreads();

    // scan over 1024 chunk sums: thread t gathers chunks 4t..4t+3 (LDS.128)
    float4 g4 = reinterpret_cast<float4*>(sCh)[tid];
    float local = ((g4.x + g4.y) + g4.z) + g4.w;
    float total;
    float excl = block_scan_excl(local, warp_sums, &total);  // syncs order reads/writes
    float4 p4;
    p4.x = excl;
    p4.y = p4.x + g4.x;
    p4.z = p4.y + g4.y;
    p4.w = p4.z + g4.z;
    reinterpret_cast<float4*>(sCh)[tid] = p4;
    __syncthreads();

#pragma unroll
    for (int i = 0; i < CPT; i++) pfx[i] = sCh[tid + TPB * i];
    *totalp = total;
}

// ---------------------------------------------------------------------------
__global__ void __launch_bounds__(TPB, 7) wasserstein_kernel(
    const float* __restrict__ f, const float* __restrict__ obs,
    const float* __restrict__ t, float* __restrict__ out)
{
    __shared__ float  sCDF[NT];      // obs CDF for binary search (16 KB)
    __shared__ float  sCh[NC];       // chunk sums / prefixes (4 KB)
    __shared__ float  sLa[NC];       // last |x| per chunk (4 KB)
    __shared__ float4 scf4[NP];      // spline coeffs
    __shared__ float  sQ[NP];
    __shared__ float  sM[NP];
    __shared__ float  sdp[98];
    __shared__ float  warp_sums[NWARP];
    __shared__ float  red[NWARP];

    const int   row = blockIdx.x;
    const int   tid = threadIdx.x;
    const float dt  = t[1] - t[0];

    float fa[CPT][4], pfx[CPT];
    float total;

    // ================= Phase A: obs -> spline coefficients =================
    chunk_scan(reinterpret_cast<const float4*>(obs + (size_t)row * NT), dt,
               fa, pfx, sCh, sLa, warp_sums, &total);

    // write element-level CDF (STS.128 per chunk)
#pragma unroll
    for (int i = 0; i < CPT; i++) {
        int c = tid + TPB * i;
        float prev = (c == 0) ? 0.0f : sLa[c - 1];
        float S = pfx[i];
        float4 o;
        S += (c == 0) ? 0.0f : 0.5f * dt * (fa[i][0] + prev);  o.x = S;
        S += 0.5f * dt * (fa[i][1] + fa[i][0]);                o.y = S;
        S += 0.5f * dt * (fa[i][2] + fa[i][1]);                o.z = S;
        S += 0.5f * dt * (fa[i][3] + fa[i][2]);                o.w = S;
        reinterpret_cast<float4*>(sCDF)[c] = o;
    }
    __syncthreads();

    // inverse CDF at 100 quantiles (binary search)
    if (tid < NP) {
        float p = (float)tid / 99.0f;
        float target = p * total;
        int lo = 0, hi = NT - 1;
        while (lo < hi) {
            int mid = (lo + hi + 1) >> 1;
            if (sCDF[mid] <= target) lo = mid; else hi = mid - 1;
        }
        int j = min(lo, NT - 2);
        float den = sCDF[j + 1] - sCDF[j];
        float q = (float)j * dt;
        if (den > 0.0f) q += (target - sCDF[j]) * dt / den;
        sQ[tid] = q;
    }
    __syncthreads();

    // u_i = rhs_i * cp_i in parallel (98 threads)
    if (tid < 98) {
        const float S6 = 6.0f * 9801.0f;   // 6 / h^2
        float rhs = S6 * (sQ[tid + 2] - 2.0f * sQ[tid + 1] + sQ[tid]);
        sdp[tid] = rhs * d_cp.v[tid];
    }
    __syncthreads();

    // serial Thomas recurrences (single FFMA chains)
    if (tid == 0) {
        float dp = sdp[0];
        for (int i = 1; i < 98; i++) {
            dp = fmaf(-d_cp.v[i], dp, sdp[i]);
            sdp[i] = dp;
        }
        sM[0] = 0.0f;
        sM[NP - 1] = 0.0f;
        float mnext = sdp[97];
        sM[98] = mnext;
        for (int i = 96; i >= 0; i--) {
            mnext = fmaf(-d_cp.v[i], mnext, sdp[i]);
            sM[i + 1] = mnext;
        }
    }
    __syncthreads();

    if (tid < NI) {
        const float H    = (float)(1.0 / 99.0);
        const float invH = 99.0f;
        float Mi = sM[tid], Mi1 = sM[tid + 1];
        float4 c;
        c.x = sQ[tid];
        c.y = (sQ[tid + 1] - sQ[tid]) * invH - H * (2.0f * Mi + Mi1) * (1.0f / 6.0f);
        c.z = Mi * 0.5f;
        c.w = (Mi1 - Mi) * (invH / 6.0f);
        scf4[tid] = c;
    }
    __syncthreads();

    // ================= Phase B: f -> loss contribution =================
    chunk_scan(reinterpret_cast<const float4*>(f + (size_t)row * NT), dt,
               fa, pfx, sCh, sLa, warp_sums, &total);

    const float invT = 1.0f / total;
    float gsum = 0.0f;
#pragma unroll
    for (int i = 0; i < CPT; i++) {
        int c = tid + TPB * i;
        float prev = (c == 0) ? 0.0f : sLa[c - 1];
        float S = pfx[i];
#pragma unroll
        for (int k = 0; k < 4; k++) {
            int j = 4 * c + k;
            float left = (k == 0) ? prev : fa[i][k - 1];
            float e = (j == 0) ? 0.0f : 0.5f * dt * (fa[i][k] + left);
            S += e;

            float xi = fminf(S * invT, 1.0f);
            int idx = min((int)(xi * 99.0f), NI - 1);
            float dx = xi - (float)idx * (float)(1.0 / 99.0);
            float4 cf = scf4[idx];
            float val = cf.x + dx * (cf.y + dx * (cf.z + dx * cf.w));
            float diff = (float)j * dt - val;
            float g = diff * diff * (fa[i][k] * invT);
            gsum += g;
            if (j == 0 || j == NT - 1) gsum -= 0.5f * g;   // trapezoid edges
        }
    }

#pragma unroll
    for (int o = 16; o; o >>= 1) gsum += __shfl_down_sync(0xffffffffu, gsum, o);
    if ((tid & 31) == 0) red[tid >> 5] = gsum;
    __syncthreads();

    if (tid == 0) {
        float s = 0.0f;
#pragma unroll
        for (int w = 0; w < NWARP; w++) s += red[w];
        double my = (double)(dt * s);
        atomicAdd(&g_acc[row & (NACC - 1)], my);
        __threadfence();
        unsigned tk = atomicInc(&g_ticket, NSNR - 1);   // wraps to 0 automatically
        if (tk == NSNR - 1) {
            double tot = 0.0;
#pragma unroll
            for (int w = 0; w < NACC; w++) { tot += g_acc[w]; g_acc[w] = 0.0; }
            out[0] = (float)tot;
        }
    }
}

// ---------------------------------------------------------------------------
extern "C" void kernel_launch(void* const* d_in, const int* in_sizes, int n_in,
                              void* d_out, int out_size)
{
    const float* f   = (const float*)d_in[0];
    const float* obs = (const float*)d_in[1];
    const float* t   = (const float*)d_in[2];

    wasserstein_kernel<<<NSNR, TPB>>>(f, obs, t, (float*)d_out);
}